// round 12
// baseline (speedup 1.0000x reference)
#include <cuda_runtime.h>
#include <cstdint>

// ---------------- problem constants ----------------
#define B_DIM 4096
#define H_DIM 2048
#define C_DIM 4096              // K dimension (H + I)
#define TM 64                   // CTA M tile (halved: 2 CTAs/SM)
#define TN 64                   // CTA N tile (per gate; x4 gates)
#define TK 32                   // K per stage
#define KSTAGES (C_DIM / TK)    // 128
#define NS 2                    // pipeline stages
#define NTHREADS 128            // 4 warps: wm=1 x wn=4

// padded smem layout: rows of 36 floats (144B) -> conflict-free frag loads
#define ROWF 36
#define A_FLOATS (TM * ROWF)            // 2304 floats
#define BG_FLOATS (TN * ROWF)           // 2304 floats
#define STAGE_FLOATS (A_FLOATS + 4 * BG_FLOATS)   // 11520 floats = 46080 B
#define SMEM_TOTAL (NS * STAGE_FLOATS * 4)        // 92160 B  (2 CTAs/SM fit)

#define HOUT_OFF 8388608        // 4096*2048 ; c_t follows h_t in d_out

// ---------- pre-rounded (tf32-rna) operand scratch ----------
__device__ float g_W[4ll * 2048 * 4096];   // 4 gates x [2048][4096]
__device__ float g_A[4096ll * 4096];       // [B][h_prev | x_t]

__device__ __forceinline__ uint32_t smem_u32(const void* p) {
    uint32_t a;
    asm("{ .reg .u64 t; cvta.to.shared.u64 t, %1; cvt.u32.u64 %0, t; }" : "=r"(a) : "l"(p));
    return a;
}

#define CP_ASYNC16(dst, src) \
    asm volatile("cp.async.cg.shared.global [%0], [%1], 16;" :: "r"(dst), "l"(src) : "memory")
#define CP_COMMIT() asm volatile("cp.async.commit_group;" ::: "memory")
#define CP_WAIT0()  asm volatile("cp.async.wait_group 0;" ::: "memory")

__device__ __forceinline__ float f2tf32f(float x) {
    uint32_t r;
    asm("cvt.rna.tf32.f32 %0, %1;" : "=r"(r) : "f"(x));
    return __uint_as_float(r);
}

__device__ __forceinline__ void mma_tf32(float* c, const uint32_t* a, const uint32_t* b) {
    asm volatile(
        "mma.sync.aligned.m16n8k8.row.col.f32.tf32.tf32.f32 "
        "{%0,%1,%2,%3}, {%4,%5,%6,%7}, {%8,%9}, {%0,%1,%2,%3};"
        : "+f"(c[0]), "+f"(c[1]), "+f"(c[2]), "+f"(c[3])
        : "r"(a[0]), "r"(a[1]), "r"(a[2]), "r"(a[3]), "r"(b[0]), "r"(b[1]));
}

__device__ __forceinline__ float sigmoidf_(float x) {
    return 1.0f / (1.0f + __expf(-x));
}
__device__ __forceinline__ float tanhf_(float x) {
    float a = fabsf(x);
    float e = __expf(-2.0f * a);
    float t = (1.0f - e) / (1.0f + e);
    return x < 0.0f ? -t : t;
}

// ---------------- prepass: round everything to tf32 (rna) once ----------------
#define W_F4 8388608
#define A_F4 4194304
#define TOT_F4 (W_F4 + A_F4)

__global__ void __launch_bounds__(256) prepass_kernel(
    const float4* __restrict__ x_t, const float4* __restrict__ h_prev,
    const float4* __restrict__ Wf, const float4* __restrict__ Wi,
    const float4* __restrict__ Wc, const float4* __restrict__ Wo)
{
    float4* __restrict__ gw = (float4*)g_W;
    float4* __restrict__ ga = (float4*)g_A;
    const int stride = gridDim.x * blockDim.x;
    for (long long i = blockIdx.x * blockDim.x + threadIdx.x; i < TOT_F4; i += stride) {
        float4 v;
        float4* dst;
        if (i < W_F4) {
            const long long g = i >> 21;
            const long long r = i & 2097151;
            const float4* wp = (g == 0) ? Wf : (g == 1) ? Wi : (g == 2) ? Wc : Wo;
            v = wp[r];
            dst = gw + i;
        } else {
            const long long j = i - W_F4;
            const long long row = j >> 10;
            const long long c4 = j & 1023;
            v = (c4 < 512) ? h_prev[row * 512 + c4] : x_t[row * 512 + (c4 - 512)];
            dst = ga + j;
        }
        v.x = f2tf32f(v.x); v.y = f2tf32f(v.y);
        v.z = f2tf32f(v.z); v.w = f2tf32f(v.w);
        *dst = v;
    }
}

// issue cp.async for one K-stage of TK=32 (all 128 threads participate)
__device__ __forceinline__ void load_stage(int ks, int stage, int tid, uint32_t sbase,
                                           int m0, int n0)
{
    const int k0 = ks * TK;
    const uint32_t stg = sbase + (uint32_t)stage * (STAGE_FLOATS * 4);
    const float* asrc = g_A + (size_t)m0 * C_DIM + k0;
    // A tile: 64 rows x 8 x 16B chunks = 512; 4 per thread
    #pragma unroll
    for (int i = 0; i < 4; i++) {
        const int c = tid + i * NTHREADS;
        const int row = c >> 3;
        const int c16 = c & 7;
        const uint32_t dst = stg + (uint32_t)(row * (ROWF * 4) + c16 * 16);
        CP_ASYNC16(dst, asrc + (size_t)row * C_DIM + c16 * 4);
    }
    // W tiles: 4 gates x 64 rows x 8 chunks = 2048; 16 per thread
    #pragma unroll
    for (int i = 0; i < 16; i++) {
        const int idx = tid + i * NTHREADS;      // 0..2047
        const int g = idx >> 9;
        const int rem = idx & 511;
        const int row = rem >> 3;
        const int c16 = rem & 7;
        const float* wp = g_W + (size_t)g * (2048ll * 4096);
        const uint32_t dst = stg + (uint32_t)(A_FLOATS * 4 + g * (BG_FLOATS * 4)
                                              + row * (ROWF * 4) + c16 * 16);
        CP_ASYNC16(dst, wp + (size_t)(n0 + row) * C_DIM + k0 + c16 * 4);
    }
}

__global__ void __launch_bounds__(NTHREADS, 2) lstm_mma_kernel(
    const float* __restrict__ c_prev,
    const float* __restrict__ bf, const float* __restrict__ bi,
    const float* __restrict__ bc, const float* __restrict__ bo,
    float* __restrict__ out)
{
    extern __shared__ float smemf[];
    const uint32_t sbase = smem_u32(smemf);
    const int tid = threadIdx.x;
    const int wid = tid >> 5;
    const int lane = tid & 31;
    const int wn = wid;          // 4 warps over N (16 cols each, nt=2); all warps span TM=64 (mt=4)
    const int gid = lane >> 2;   // mma groupID
    const int tig = lane & 3;    // mma threadID_in_group
    const int m0 = blockIdx.x * TM;
    const int n0 = blockIdx.y * TN;

    // accumulators: [gate][mt=4][nt=2][4] = 128 floats
    float acc[4][4][2][4];
    #pragma unroll
    for (int g = 0; g < 4; g++)
        #pragma unroll
        for (int mt = 0; mt < 4; mt++)
            #pragma unroll
            for (int nt = 0; nt < 2; nt++)
                #pragma unroll
                for (int r = 0; r < 4; r++) acc[g][mt][nt][r] = 0.0f;

    // prologue: stage 0
    load_stage(0, 0, tid, sbase, m0, n0);
    CP_COMMIT();

    #pragma unroll 1
    for (int ks = 0; ks < KSTAGES; ks++) {
        CP_WAIT0();                // stage ks landed (only group in flight)
        __syncthreads();           // publish stage ks; protect buffer (ks+1)&1
        if (ks + 1 < KSTAGES) {
            load_stage(ks + 1, (ks + 1) & 1, tid, sbase, m0, n0);
            CP_COMMIT();
        }
        const uint32_t* As = (const uint32_t*)(smemf + (ks & 1) * STAGE_FLOATS);
        const uint32_t* Bs = As + A_FLOATS;

        #pragma unroll
        for (int kk = 0; kk < 4; kk++) {
            const int kc = kk * 8;
            uint32_t afr[4][4];
            #pragma unroll
            for (int mt = 0; mt < 4; mt++) {
                const int r0 = mt * 16 + gid;
                afr[mt][0] = As[r0 * ROWF + kc + tig];
                afr[mt][1] = As[(r0 + 8) * ROWF + kc + tig];
                afr[mt][2] = As[r0 * ROWF + kc + tig + 4];
                afr[mt][3] = As[(r0 + 8) * ROWF + kc + tig + 4];
            }
            #pragma unroll
            for (int g = 0; g < 4; g++) {
                const uint32_t* Bg = Bs + g * BG_FLOATS;
                uint32_t bfr[2][2];
                #pragma unroll
                for (int nt = 0; nt < 2; nt++) {
                    const int nb = wn * 16 + nt * 8 + gid;
                    bfr[nt][0] = Bg[nb * ROWF + kc + tig];
                    bfr[nt][1] = Bg[nb * ROWF + kc + tig + 4];
                }
                #pragma unroll
                for (int mt = 0; mt < 4; mt++)
                    #pragma unroll
                    for (int nt = 0; nt < 2; nt++)
                        mma_tf32(acc[g][mt][nt], afr[mt], bfr[nt]);
            }
        }
    }

    // ---------------- fused LSTM epilogue (registers only) ----------------
    #pragma unroll
    for (int nt = 0; nt < 2; nt++) {
        const int col = n0 + wn * 16 + nt * 8 + tig * 2;
        const float2 bf2 = *(const float2*)(bf + col);
        const float2 bi2 = *(const float2*)(bi + col);
        const float2 bc2 = *(const float2*)(bc + col);
        const float2 bo2 = *(const float2*)(bo + col);
        #pragma unroll
        for (int mt = 0; mt < 4; mt++) {
            const int row0 = m0 + mt * 16 + gid;
            #pragma unroll
            for (int half = 0; half < 2; half++) {
                const int row = row0 + half * 8;
                const int ci = half * 2;
                const float2 cp = *(const float2*)(c_prev + (size_t)row * H_DIM + col);
                float hh[2], cc[2];
                #pragma unroll
                for (int j = 0; j < 2; j++) {
                    const float gf = acc[0][mt][nt][ci + j] + (j ? bf2.y : bf2.x);
                    const float gi = acc[1][mt][nt][ci + j] + (j ? bi2.y : bi2.x);
                    const float gc = acc[2][mt][nt][ci + j] + (j ? bc2.y : bc2.x);
                    const float go = acc[3][mt][nt][ci + j] + (j ? bo2.y : bo2.x);
                    const float f = sigmoidf_(gf);
                    const float i = sigmoidf_(gi);
                    const float ct = tanhf_(gc);
                    const float o = sigmoidf_(go);
                    const float c = f * (j ? cp.y : cp.x) + i * ct;
                    cc[j] = c;
                    hh[j] = o * tanhf_(c);
                }
                *(float2*)(out + (size_t)row * H_DIM + col) = make_float2(hh[0], hh[1]);
                *(float2*)(out + HOUT_OFF + (size_t)row * H_DIM + col) = make_float2(cc[0], cc[1]);
            }
        }
    }
}

extern "C" void kernel_launch(void* const* d_in, const int* in_sizes, int n_in,
                              void* d_out, int out_size) {
    const float* x_t    = (const float*)d_in[0];
    const float* h_prev = (const float*)d_in[1];
    const float* c_prev = (const float*)d_in[2];
    const float* W_f    = (const float*)d_in[3];
    const float* b_f    = (const float*)d_in[4];
    const float* W_i    = (const float*)d_in[5];
    const float* b_i    = (const float*)d_in[6];
    const float* W_c    = (const float*)d_in[7];
    const float* b_c    = (const float*)d_in[8];
    const float* W_o    = (const float*)d_in[9];
    const float* b_o    = (const float*)d_in[10];
    float* out = (float*)d_out;

    // 1) round all GEMM operands to tf32 once
    prepass_kernel<<<2048, 256>>>(
        (const float4*)x_t, (const float4*)h_prev,
        (const float4*)W_f, (const float4*)W_i,
        (const float4*)W_c, (const float4*)W_o);

    // 2) fused GEMM + LSTM epilogue (2 CTAs/SM -> desynchronized barriers)
    cudaFuncSetAttribute(lstm_mma_kernel,
                         cudaFuncAttributeMaxDynamicSharedMemorySize, SMEM_TOTAL);
    dim3 grid(B_DIM / TM, H_DIM / TN);   // (64, 32)
    lstm_mma_kernel<<<grid, NTHREADS, SMEM_TOTAL>>>(
        c_prev, b_f, b_i, b_c, b_o, out);
}

// round 13
// speedup vs baseline: 1.3224x; 1.3224x over previous
#include <cuda_runtime.h>
#include <cstdint>

// ---------------- problem constants ----------------
#define B_DIM 4096
#define H_DIM 2048
#define C_DIM 4096              // K dimension (H + I)
#define TM 128                  // CTA M tile
#define TN 64                   // CTA N tile (per gate; x4 gates)
#define TK 64                   // K per stage
#define KSTAGES (C_DIM / TK)    // 64
#define NS 2                    // pipeline stages
#define NTHREADS 256            // 8 warps: wm(2) x wn(4); mt=4, nt=2

// fragment-major smem: A = 2048 float4 (32 KB), W = 4096 float4 (64 KB)
#define A_F4S 2048
#define W_F4S 4096
#define STAGE_FLOATS ((A_F4S + W_F4S) * 4)        // 24576 floats = 98304 B
#define SMEM_TOTAL (NS * STAGE_FLOATS * 4)        // 196608 B

#define HOUT_OFF 8388608        // 4096*2048 ; c_t follows h_t in d_out

// ---------- pre-rounded + fragment-permuted operand scratch ----------
// g_A: [mtile(32)][kstage(64)][kb(8)][bm(8)][lane(32)] float4  (64 MB)
// g_W: [ntile(32)][kstage(64)][gate(4)][kb(8)][np(4)][lane(32)] float4 (128 MB)
__device__ float4 g_A[32ll * 64 * 2048];
__device__ float4 g_W[32ll * 64 * 4096];

__device__ __forceinline__ uint32_t smem_u32(const void* p) {
    uint32_t a;
    asm("{ .reg .u64 t; cvta.to.shared.u64 t, %1; cvt.u32.u64 %0, t; }" : "=r"(a) : "l"(p));
    return a;
}

#define CP_ASYNC16(dst, src) \
    asm volatile("cp.async.cg.shared.global [%0], [%1], 16;" :: "r"(dst), "l"(src) : "memory")
#define CP_COMMIT() asm volatile("cp.async.commit_group;" ::: "memory")
#define CP_WAIT0()  asm volatile("cp.async.wait_group 0;" ::: "memory")

__device__ __forceinline__ float f2tf32f(float x) {
    uint32_t r;
    asm("cvt.rna.tf32.f32 %0, %1;" : "=r"(r) : "f"(x));
    return __uint_as_float(r);
}

__device__ __forceinline__ void mma_tf32(float* c, const uint32_t* a, const uint32_t* b) {
    asm volatile(
        "mma.sync.aligned.m16n8k8.row.col.f32.tf32.tf32.f32 "
        "{%0,%1,%2,%3}, {%4,%5,%6,%7}, {%8,%9}, {%0,%1,%2,%3};"
        : "+f"(c[0]), "+f"(c[1]), "+f"(c[2]), "+f"(c[3])
        : "r"(a[0]), "r"(a[1]), "r"(a[2]), "r"(a[3]), "r"(b[0]), "r"(b[1]));
}

__device__ __forceinline__ float sigmoidf_(float x) {
    return 1.0f / (1.0f + __expf(-x));
}
__device__ __forceinline__ float tanhf_(float x) {
    float a = fabsf(x);
    float e = __expf(-2.0f * a);
    float t = (1.0f - e) / (1.0f + e);
    return x < 0.0f ? -t : t;
}

// ---------------- prepass: round to tf32 AND permute to fragment-major ----------
#define A_CHUNKS 4194304          // 32*64*64*32
#define W_CHUNKS 8388608          // 32*64*4*8*4*32
#define TOT_CHUNKS (A_CHUNKS + W_CHUNKS)

__global__ void __launch_bounds__(256) prepass_kernel(
    const float* __restrict__ x_t, const float* __restrict__ h_prev,
    const float* __restrict__ Wf, const float* __restrict__ Wi,
    const float* __restrict__ Wc, const float* __restrict__ Wo)
{
    const int stride = gridDim.x * blockDim.x;
    for (long long i = blockIdx.x * blockDim.x + threadIdx.x; i < TOT_CHUNKS; i += stride) {
        float4 v;
        if (i < A_CHUNKS) {
            // [mtile][kstage][kb][bm][lane]
            const int l   = (int)(i) & 31;
            const int bm  = ((int)(i >> 5)) & 7;
            const int kb  = ((int)(i >> 8)) & 7;
            const int kst = ((int)(i >> 11)) & 63;
            const int mti = (int)(i >> 17);
            const int gid = l >> 2, tig = l & 3;
            const int r = mti * 128 + bm * 16 + gid;
            const int c = kst * 64 + kb * 8 + tig;       // 8-col block never crosses 2048
            const float* src = (c < H_DIM)
                ? (h_prev + (size_t)r * H_DIM + c)
                : (x_t + (size_t)r * H_DIM + (c - H_DIM));
            v.x = f2tf32f(src[0]);
            v.y = f2tf32f(src[8 * H_DIM]);
            v.z = f2tf32f(src[4]);
            v.w = f2tf32f(src[8 * H_DIM + 4]);
            g_A[i] = v;
        } else {
            // [ntile][kstage][gate][kb][np][lane]
            const long long j = i - A_CHUNKS;
            const int l    = (int)(j) & 31;
            const int np   = ((int)(j >> 5)) & 3;
            const int kb   = ((int)(j >> 7)) & 7;
            const int gate = ((int)(j >> 10)) & 3;
            const int kst  = ((int)(j >> 12)) & 63;
            const int nti  = (int)(j >> 18);
            const int gid = l >> 2, tig = l & 3;
            const int n = nti * 64 + np * 16 + gid;
            const int k = kst * 64 + kb * 8 + tig;
            const float* wp = (gate == 0) ? Wf : (gate == 1) ? Wi : (gate == 2) ? Wc : Wo;
            const float* s0 = wp + (size_t)n * C_DIM + k;
            v.x = f2tf32f(s0[0]);                        // B[k+tig][n]       (nt=0)
            v.y = f2tf32f(s0[4]);                        // B[k+tig+4][n]
            v.z = f2tf32f(s0[8 * C_DIM]);                // B[k+tig][n+8]     (nt=1)
            v.w = f2tf32f(s0[8 * C_DIM + 4]);            // B[k+tig+4][n+8]
            g_W[j] = v;
        }
    }
}

// issue cp.async for one K-stage (fully contiguous, coalesced)
__device__ __forceinline__ void load_stage(int ks, int stage, int tid, uint32_t sbase,
                                           int m0, int n0)
{
    const uint32_t stg = sbase + (uint32_t)stage * (STAGE_FLOATS * 4);
    const float4* asrc = g_A + ((size_t)(m0 >> 7) * 64 + ks) * A_F4S;
    #pragma unroll
    for (int i = 0; i < 8; i++) {
        const int c = tid + i * NTHREADS;
        CP_ASYNC16(stg + c * 16, asrc + c);
    }
    const float4* wsrc = g_W + ((size_t)(n0 >> 6) * 64 + ks) * W_F4S;
    #pragma unroll
    for (int i = 0; i < 16; i++) {
        const int c = tid + i * NTHREADS;
        CP_ASYNC16(stg + A_F4S * 16 + c * 16, wsrc + c);
    }
}

__global__ void __launch_bounds__(NTHREADS, 1) lstm_mma_kernel(
    const float* __restrict__ c_prev,
    const float* __restrict__ bf, const float* __restrict__ bi,
    const float* __restrict__ bc, const float* __restrict__ bo,
    float* __restrict__ out)
{
    extern __shared__ float smemf[];
    const uint32_t sbase = smem_u32(smemf);
    const int tid = threadIdx.x;
    const int wid = tid >> 5;
    const int lane = tid & 31;
    const int wm = wid & 1;      // 2 warps over M (64 rows each, mt=4)
    const int wn = wid >> 1;     // 4 warps over N (16 cols each, nt=2)
    const int gid = lane >> 2;
    const int tig = lane & 3;
    const int m0 = blockIdx.x * TM;
    const int n0 = blockIdx.y * TN;

    // accumulators: [gate][mt=4][nt=2][4] = 128 floats
    float acc[4][4][2][4];
    #pragma unroll
    for (int g = 0; g < 4; g++)
        #pragma unroll
        for (int mt = 0; mt < 4; mt++)
            #pragma unroll
            for (int nt = 0; nt < 2; nt++)
                #pragma unroll
                for (int r = 0; r < 4; r++) acc[g][mt][nt][r] = 0.0f;

    load_stage(0, 0, tid, sbase, m0, n0);
    CP_COMMIT();

    #pragma unroll 1
    for (int ks = 0; ks < KSTAGES; ks++) {
        CP_WAIT0();
        __syncthreads();
        if (ks + 1 < KSTAGES) {
            load_stage(ks + 1, (ks + 1) & 1, tid, sbase, m0, n0);
            CP_COMMIT();
        }
        const float4* As4 = (const float4*)(smemf + (ks & 1) * STAGE_FLOATS);
        const float4* Ws4 = As4 + A_F4S;

        #pragma unroll
        for (int kk = 0; kk < 8; kk++) {
            // A fragments: one LDS.128 per mt
            float4 af[4];
            #pragma unroll
            for (int mt = 0; mt < 4; mt++)
                af[mt] = As4[(kk * 8 + wm * 4 + mt) * 32 + lane];
            #pragma unroll
            for (int g = 0; g < 4; g++) {
                // B fragment pair (nt=0,1) in one LDS.128
                const float4 wv = Ws4[g * 1024 + (kk * 4 + wn) * 32 + lane];
                uint32_t b0[2], b1[2];
                b0[0] = __float_as_uint(wv.x); b0[1] = __float_as_uint(wv.y);
                b1[0] = __float_as_uint(wv.z); b1[1] = __float_as_uint(wv.w);
                #pragma unroll
                for (int mt = 0; mt < 4; mt++) {
                    mma_tf32(acc[g][mt][0], (const uint32_t*)&af[mt], b0);
                    mma_tf32(acc[g][mt][1], (const uint32_t*)&af[mt], b1);
                }
            }
        }
    }

    // ---------------- fused LSTM epilogue (registers only) ----------------
    #pragma unroll
    for (int nt = 0; nt < 2; nt++) {
        const int col = n0 + wn * 16 + nt * 8 + tig * 2;
        const float2 bf2 = *(const float2*)(bf + col);
        const float2 bi2 = *(const float2*)(bi + col);
        const float2 bc2 = *(const float2*)(bc + col);
        const float2 bo2 = *(const float2*)(bo + col);
        #pragma unroll
        for (int mt = 0; mt < 4; mt++) {
            const int row0 = m0 + wm * 64 + mt * 16 + gid;
            #pragma unroll
            for (int half = 0; half < 2; half++) {
                const int row = row0 + half * 8;
                const int ci = half * 2;
                const float2 cp = *(const float2*)(c_prev + (size_t)row * H_DIM + col);
                float hh[2], cc[2];
                #pragma unroll
                for (int j = 0; j < 2; j++) {
                    const float gf = acc[0][mt][nt][ci + j] + (j ? bf2.y : bf2.x);
                    const float gi = acc[1][mt][nt][ci + j] + (j ? bi2.y : bi2.x);
                    const float gc = acc[2][mt][nt][ci + j] + (j ? bc2.y : bc2.x);
                    const float go = acc[3][mt][nt][ci + j] + (j ? bo2.y : bo2.x);
                    const float f = sigmoidf_(gf);
                    const float i = sigmoidf_(gi);
                    const float ct = tanhf_(gc);
                    const float o = sigmoidf_(go);
                    const float c = f * (j ? cp.y : cp.x) + i * ct;
                    cc[j] = c;
                    hh[j] = o * tanhf_(c);
                }
                *(float2*)(out + (size_t)row * H_DIM + col) = make_float2(hh[0], hh[1]);
                *(float2*)(out + HOUT_OFF + (size_t)row * H_DIM + col) = make_float2(cc[0], cc[1]);
            }
        }
    }
}

extern "C" void kernel_launch(void* const* d_in, const int* in_sizes, int n_in,
                              void* d_out, int out_size) {
    const float* x_t    = (const float*)d_in[0];
    const float* h_prev = (const float*)d_in[1];
    const float* c_prev = (const float*)d_in[2];
    const float* W_f    = (const float*)d_in[3];
    const float* b_f    = (const float*)d_in[4];
    const float* W_i    = (const float*)d_in[5];
    const float* b_i    = (const float*)d_in[6];
    const float* W_c    = (const float*)d_in[7];
    const float* b_c    = (const float*)d_in[8];
    const float* W_o    = (const float*)d_in[9];
    const float* b_o    = (const float*)d_in[10];
    float* out = (float*)d_out;

    // 1) round to tf32 + permute to fragment-major layout
    prepass_kernel<<<4096, 256>>>(x_t, h_prev, W_f, W_i, W_c, W_o);

    // 2) fused GEMM + LSTM epilogue (LDS.128 fragment loads)
    cudaFuncSetAttribute(lstm_mma_kernel,
                         cudaFuncAttributeMaxDynamicSharedMemorySize, SMEM_TOTAL);
    dim3 grid(B_DIM / TM, H_DIM / TN);   // (32, 32)
    lstm_mma_kernel<<<grid, NTHREADS, SMEM_TOTAL>>>(
        c_prev, b_f, b_i, b_c, b_o, out);
}

// round 14
// speedup vs baseline: 1.3966x; 1.0561x over previous
#include <cuda_runtime.h>
#include <cstdint>

// ---------------- problem constants ----------------
#define B_DIM 4096
#define H_DIM 2048
#define C_DIM 4096              // K dimension (H + I)
#define TM 128                  // CTA M tile
#define TN 64                   // CTA N tile (per gate; x4 gates)
#define TK 32                   // K per stage
#define KSTAGES (C_DIM / TK)    // 128
#define NS 4                    // pipeline stages (wait_group 2 -> 3 stages slack)
#define NTHREADS 256            // 8 warps: wm(2) x wn(4); mt=4, nt=2

// fragment-major smem per stage: A = 1024 float4 (16 KB), W = 2048 float4 (32 KB)
#define A_F4S 1024
#define W_F4S 2048
#define STAGE_F4 (A_F4S + W_F4S)                  // 3072 float4 = 48 KB
#define SMEM_TOTAL (NS * STAGE_F4 * 16)           // 196608 B

#define HOUT_OFF 8388608        // 4096*2048 ; c_t follows h_t in d_out

// ---------- pre-rounded + fragment-permuted operand scratch ----------
// g_A: [mtile(32)][kstage(128)][kb(4)][bm(8)][lane(32)] float4  (64 MB)
// g_W: [ntile(32)][kstage(128)][gate(4)][kb(4)][np(4)][lane(32)] float4 (128 MB)
__device__ float4 g_A[32ll * 128 * 1024];
__device__ float4 g_W[32ll * 128 * 2048];

__device__ __forceinline__ uint32_t smem_u32(const void* p) {
    uint32_t a;
    asm("{ .reg .u64 t; cvta.to.shared.u64 t, %1; cvt.u32.u64 %0, t; }" : "=r"(a) : "l"(p));
    return a;
}

#define CP_ASYNC16(dst, src) \
    asm volatile("cp.async.cg.shared.global [%0], [%1], 16;" :: "r"(dst), "l"(src) : "memory")
#define CP_COMMIT() asm volatile("cp.async.commit_group;" ::: "memory")
#define CP_WAITN(n) asm volatile("cp.async.wait_group %0;" :: "n"(n) : "memory")

__device__ __forceinline__ float f2tf32f(float x) {
    uint32_t r;
    asm("cvt.rna.tf32.f32 %0, %1;" : "=r"(r) : "f"(x));
    return __uint_as_float(r);
}

__device__ __forceinline__ void mma_tf32(float* c, const uint32_t* a, const uint32_t* b) {
    asm volatile(
        "mma.sync.aligned.m16n8k8.row.col.f32.tf32.tf32.f32 "
        "{%0,%1,%2,%3}, {%4,%5,%6,%7}, {%8,%9}, {%0,%1,%2,%3};"
        : "+f"(c[0]), "+f"(c[1]), "+f"(c[2]), "+f"(c[3])
        : "r"(a[0]), "r"(a[1]), "r"(a[2]), "r"(a[3]), "r"(b[0]), "r"(b[1]));
}

__device__ __forceinline__ float sigmoidf_(float x) {
    return 1.0f / (1.0f + __expf(-x));
}
__device__ __forceinline__ float tanhf_(float x) {
    float a = fabsf(x);
    float e = __expf(-2.0f * a);
    float t = (1.0f - e) / (1.0f + e);
    return x < 0.0f ? -t : t;
}

// ---------------- prepass: round to tf32 AND permute to fragment-major ----------
#define A_CHUNKS 4194304          // 32*128*4*8*32
#define W_CHUNKS 8388608          // 32*128*4*4*4*32
#define TOT_CHUNKS (A_CHUNKS + W_CHUNKS)

__global__ void __launch_bounds__(256) prepass_kernel(
    const float* __restrict__ x_t, const float* __restrict__ h_prev,
    const float* __restrict__ Wf, const float* __restrict__ Wi,
    const float* __restrict__ Wc, const float* __restrict__ Wo)
{
    const int stride = gridDim.x * blockDim.x;
    for (long long i = blockIdx.x * blockDim.x + threadIdx.x; i < TOT_CHUNKS; i += stride) {
        float4 v;
        if (i < A_CHUNKS) {
            // [mtile][kstage(128)][kb(4)][bm(8)][lane]
            const int l   = (int)(i) & 31;
            const int bm  = ((int)(i >> 5)) & 7;
            const int kb  = ((int)(i >> 8)) & 3;
            const int kst = ((int)(i >> 10)) & 127;
            const int mti = (int)(i >> 17);
            const int gid = l >> 2, tig = l & 3;
            const int r = mti * 128 + bm * 16 + gid;
            const int c = kst * 32 + kb * 8 + tig;       // 8-col block never crosses 2048
            const float* src = (c < H_DIM)
                ? (h_prev + (size_t)r * H_DIM + c)
                : (x_t + (size_t)r * H_DIM + (c - H_DIM));
            v.x = f2tf32f(src[0]);
            v.y = f2tf32f(src[8 * H_DIM]);
            v.z = f2tf32f(src[4]);
            v.w = f2tf32f(src[8 * H_DIM + 4]);
            g_A[i] = v;
        } else {
            // [ntile][kstage(128)][gate(4)][kb(4)][np(4)][lane]
            const long long j = i - A_CHUNKS;
            const int l    = (int)(j) & 31;
            const int np   = ((int)(j >> 5)) & 3;
            const int kb   = ((int)(j >> 7)) & 3;
            const int gate = ((int)(j >> 9)) & 3;
            const int kst  = ((int)(j >> 11)) & 127;
            const int nti  = (int)(j >> 18);
            const int gid = l >> 2, tig = l & 3;
            const int n = nti * 64 + np * 16 + gid;
            const int k = kst * 32 + kb * 8 + tig;
            const float* wp = (gate == 0) ? Wf : (gate == 1) ? Wi : (gate == 2) ? Wc : Wo;
            const float* s0 = wp + (size_t)n * C_DIM + k;
            v.x = f2tf32f(s0[0]);                        // B[k+tig][n]       (nt=0)
            v.y = f2tf32f(s0[4]);                        // B[k+tig+4][n]
            v.z = f2tf32f(s0[8 * C_DIM]);                // B[k+tig][n+8]     (nt=1)
            v.w = f2tf32f(s0[8 * C_DIM + 4]);            // B[k+tig+4][n+8]
            g_W[j] = v;
        }
    }
}

// issue cp.async for one K-stage (fully contiguous, coalesced): 12 chunks/thread
__device__ __forceinline__ void load_stage(int ks, int stage, int tid, uint32_t sbase,
                                           int m0, int n0)
{
    const uint32_t stg = sbase + (uint32_t)stage * (STAGE_F4 * 16);
    const float4* asrc = g_A + ((size_t)(m0 >> 7) * KSTAGES + ks) * A_F4S;
    #pragma unroll
    for (int i = 0; i < 4; i++) {
        const int c = tid + i * NTHREADS;
        CP_ASYNC16(stg + c * 16, asrc + c);
    }
    const float4* wsrc = g_W + ((size_t)(n0 >> 6) * KSTAGES + ks) * W_F4S;
    #pragma unroll
    for (int i = 0; i < 8; i++) {
        const int c = tid + i * NTHREADS;
        CP_ASYNC16(stg + A_F4S * 16 + c * 16, wsrc + c);
    }
}

__global__ void __launch_bounds__(NTHREADS, 1) lstm_mma_kernel(
    const float* __restrict__ c_prev,
    const float* __restrict__ bf, const float* __restrict__ bi,
    const float* __restrict__ bc, const float* __restrict__ bo,
    float* __restrict__ out)
{
    extern __shared__ float smemf[];
    const uint32_t sbase = smem_u32(smemf);
    const int tid = threadIdx.x;
    const int wid = tid >> 5;
    const int lane = tid & 31;
    const int wm = wid & 1;      // 2 warps over M (64 rows each, mt=4)
    const int wn = wid >> 1;     // 4 warps over N (16 cols each, nt=2)
    const int gid = lane >> 2;
    const int tig = lane & 3;
    const int m0 = blockIdx.x * TM;
    const int n0 = blockIdx.y * TN;

    // accumulators: [gate][mt=4][nt=2][4] = 128 floats
    float acc[4][4][2][4];
    #pragma unroll
    for (int g = 0; g < 4; g++)
        #pragma unroll
        for (int mt = 0; mt < 4; mt++)
            #pragma unroll
            for (int nt = 0; nt < 2; nt++)
                #pragma unroll
                for (int r = 0; r < 4; r++) acc[g][mt][nt][r] = 0.0f;

    // prologue: stages 0..2 in flight
    #pragma unroll
    for (int s = 0; s < NS - 1; s++) {
        load_stage(s, s, tid, sbase, m0, n0);
        CP_COMMIT();
    }

    #pragma unroll 1
    for (int ks = 0; ks < KSTAGES; ks++) {
        // drain enough groups that stage ks is resident
        if (ks < KSTAGES - 2)      { CP_WAITN(2); }
        else if (ks == KSTAGES - 2){ CP_WAITN(1); }
        else                       { CP_WAITN(0); }
        __syncthreads();

        const float4* As4 = (const float4*)(smemf + (ks & (NS - 1)) * (STAGE_F4 * 4));
        const float4* Ws4 = As4 + A_F4S;

        #pragma unroll
        for (int kk = 0; kk < 4; kk++) {
            float4 af[4];
            #pragma unroll
            for (int mt = 0; mt < 4; mt++)
                af[mt] = As4[(kk * 8 + wm * 4 + mt) * 32 + lane];
            #pragma unroll
            for (int g = 0; g < 4; g++) {
                const float4 wv = Ws4[g * 512 + (kk * 4 + wn) * 32 + lane];
                uint32_t b0[2], b1[2];
                b0[0] = __float_as_uint(wv.x); b0[1] = __float_as_uint(wv.y);
                b1[0] = __float_as_uint(wv.z); b1[1] = __float_as_uint(wv.w);
                #pragma unroll
                for (int mt = 0; mt < 4; mt++) {
                    mma_tf32(acc[g][mt][0], (const uint32_t*)&af[mt], b0);
                    mma_tf32(acc[g][mt][1], (const uint32_t*)&af[mt], b1);
                }
            }
            // issue next loads mid-stage, away from the post-barrier ramp
            if (kk == 0 && ks + NS - 1 < KSTAGES) {
                load_stage(ks + NS - 1, (ks + NS - 1) & (NS - 1), tid, sbase, m0, n0);
                CP_COMMIT();
            }
        }
    }

    // ---------------- fused LSTM epilogue (registers only) ----------------
    #pragma unroll
    for (int nt = 0; nt < 2; nt++) {
        const int col = n0 + wn * 16 + nt * 8 + tig * 2;
        const float2 bf2 = *(const float2*)(bf + col);
        const float2 bi2 = *(const float2*)(bi + col);
        const float2 bc2 = *(const float2*)(bc + col);
        const float2 bo2 = *(const float2*)(bo + col);
        #pragma unroll
        for (int mt = 0; mt < 4; mt++) {
            const int row0 = m0 + wm * 64 + mt * 16 + gid;
            #pragma unroll
            for (int half = 0; half < 2; half++) {
                const int row = row0 + half * 8;
                const int ci = half * 2;
                const float2 cp = *(const float2*)(c_prev + (size_t)row * H_DIM + col);
                float hh[2], cc[2];
                #pragma unroll
                for (int j = 0; j < 2; j++) {
                    const float gf = acc[0][mt][nt][ci + j] + (j ? bf2.y : bf2.x);
                    const float gi = acc[1][mt][nt][ci + j] + (j ? bi2.y : bi2.x);
                    const float gc = acc[2][mt][nt][ci + j] + (j ? bc2.y : bc2.x);
                    const float go = acc[3][mt][nt][ci + j] + (j ? bo2.y : bo2.x);
                    const float f = sigmoidf_(gf);
                    const float i = sigmoidf_(gi);
                    const float ct = tanhf_(gc);
                    const float o = sigmoidf_(go);
                    const float c = f * (j ? cp.y : cp.x) + i * ct;
                    cc[j] = c;
                    hh[j] = o * tanhf_(c);
                }
                *(float2*)(out + (size_t)row * H_DIM + col) = make_float2(hh[0], hh[1]);
                *(float2*)(out + HOUT_OFF + (size_t)row * H_DIM + col) = make_float2(cc[0], cc[1]);
            }
        }
    }
}

extern "C" void kernel_launch(void* const* d_in, const int* in_sizes, int n_in,
                              void* d_out, int out_size) {
    const float* x_t    = (const float*)d_in[0];
    const float* h_prev = (const float*)d_in[1];
    const float* c_prev = (const float*)d_in[2];
    const float* W_f    = (const float*)d_in[3];
    const float* b_f    = (const float*)d_in[4];
    const float* W_i    = (const float*)d_in[5];
    const float* b_i    = (const float*)d_in[6];
    const float* W_c    = (const float*)d_in[7];
    const float* b_c    = (const float*)d_in[8];
    const float* W_o    = (const float*)d_in[9];
    const float* b_o    = (const float*)d_in[10];
    float* out = (float*)d_out;

    // 1) round to tf32 + permute to fragment-major layout
    prepass_kernel<<<4096, 256>>>(x_t, h_prev, W_f, W_i, W_c, W_o);

    // 2) fused GEMM + LSTM epilogue (4-stage pipeline, relaxed waits)
    cudaFuncSetAttribute(lstm_mma_kernel,
                         cudaFuncAttributeMaxDynamicSharedMemorySize, SMEM_TOTAL);
    dim3 grid(B_DIM / TM, H_DIM / TN);   // (32, 32)
    lstm_mma_kernel<<<grid, NTHREADS, SMEM_TOTAL>>>(
        c_prev, b_f, b_i, b_c, b_o, out);
}

// round 15
// speedup vs baseline: 1.4498x; 1.0381x over previous
#include <cuda_runtime.h>
#include <cstdint>

// ---------------- problem constants ----------------
#define B_DIM 4096
#define H_DIM 2048
#define C_DIM 4096              // K dimension (H + I)
#define TM 128                  // CTA M tile
#define TN 64                   // CTA N tile (per gate; x4 gates)
#define TK 32                   // K per stage
#define KSTAGES (C_DIM / TK)    // 128
#define NS 4                    // pipeline buffers; barrier every 2 stages (NS >= 2P)
#define NTHREADS 256            // 8 warps: wm(2) x wn(4); mt=4, nt=2

// fragment-major smem per stage: A = 1024 float4 (16 KB), W = 2048 float4 (32 KB)
#define A_F4S 1024
#define W_F4S 2048
#define STAGE_F4 (A_F4S + W_F4S)                  // 3072 float4 = 48 KB
#define SMEM_TOTAL (NS * STAGE_F4 * 16)           // 196608 B

#define HOUT_OFF 8388608        // 4096*2048 ; c_t follows h_t in d_out

// ---------- pre-rounded + fragment-permuted operand scratch ----------
// g_A: [mtile(32)][kstage(128)][kb(4)][bm(8)][lane(32)] float4  (64 MB)
// g_W: [ntile(32)][kstage(128)][gate(4)][kb(4)][np(4)][lane(32)] float4 (128 MB)
__device__ float4 g_A[32ll * 128 * 1024];
__device__ float4 g_W[32ll * 128 * 2048];

__device__ __forceinline__ uint32_t smem_u32(const void* p) {
    uint32_t a;
    asm("{ .reg .u64 t; cvta.to.shared.u64 t, %1; cvt.u32.u64 %0, t; }" : "=r"(a) : "l"(p));
    return a;
}

#define CP_ASYNC16(dst, src) \
    asm volatile("cp.async.cg.shared.global [%0], [%1], 16;" :: "r"(dst), "l"(src) : "memory")
#define CP_COMMIT() asm volatile("cp.async.commit_group;" ::: "memory")
#define CP_WAITN(n) asm volatile("cp.async.wait_group %0;" :: "n"(n) : "memory")

__device__ __forceinline__ float f2tf32f(float x) {
    uint32_t r;
    asm("cvt.rna.tf32.f32 %0, %1;" : "=r"(r) : "f"(x));
    return __uint_as_float(r);
}

__device__ __forceinline__ void mma_tf32(float* c, const uint32_t* a, const uint32_t* b) {
    asm volatile(
        "mma.sync.aligned.m16n8k8.row.col.f32.tf32.tf32.f32 "
        "{%0,%1,%2,%3}, {%4,%5,%6,%7}, {%8,%9}, {%0,%1,%2,%3};"
        : "+f"(c[0]), "+f"(c[1]), "+f"(c[2]), "+f"(c[3])
        : "r"(a[0]), "r"(a[1]), "r"(a[2]), "r"(a[3]), "r"(b[0]), "r"(b[1]));
}

__device__ __forceinline__ float sigmoidf_(float x) {
    return 1.0f / (1.0f + __expf(-x));
}
__device__ __forceinline__ float tanhf_(float x) {
    float a = fabsf(x);
    float e = __expf(-2.0f * a);
    float t = (1.0f - e) / (1.0f + e);
    return x < 0.0f ? -t : t;
}

// ---------------- prepass: round to tf32 AND permute to fragment-major ----------
#define A_CHUNKS 4194304          // 32*128*4*8*32
#define W_CHUNKS 8388608          // 32*128*4*4*4*32
#define TOT_CHUNKS (A_CHUNKS + W_CHUNKS)

__global__ void __launch_bounds__(256) prepass_kernel(
    const float* __restrict__ x_t, const float* __restrict__ h_prev,
    const float* __restrict__ Wf, const float* __restrict__ Wi,
    const float* __restrict__ Wc, const float* __restrict__ Wo)
{
    const int stride = gridDim.x * blockDim.x;
    for (long long i = blockIdx.x * blockDim.x + threadIdx.x; i < TOT_CHUNKS; i += stride) {
        float4 v;
        if (i < A_CHUNKS) {
            // [mtile][kstage(128)][kb(4)][bm(8)][lane]
            const int l   = (int)(i) & 31;
            const int bm  = ((int)(i >> 5)) & 7;
            const int kb  = ((int)(i >> 8)) & 3;
            const int kst = ((int)(i >> 10)) & 127;
            const int mti = (int)(i >> 17);
            const int gid = l >> 2, tig = l & 3;
            const int r = mti * 128 + bm * 16 + gid;
            const int c = kst * 32 + kb * 8 + tig;       // 8-col block never crosses 2048
            const float* src = (c < H_DIM)
                ? (h_prev + (size_t)r * H_DIM + c)
                : (x_t + (size_t)r * H_DIM + (c - H_DIM));
            v.x = f2tf32f(src[0]);
            v.y = f2tf32f(src[8 * H_DIM]);
            v.z = f2tf32f(src[4]);
            v.w = f2tf32f(src[8 * H_DIM + 4]);
            g_A[i] = v;
        } else {
            // [ntile][kstage(128)][gate(4)][kb(4)][np(4)][lane]
            const long long j = i - A_CHUNKS;
            const int l    = (int)(j) & 31;
            const int np   = ((int)(j >> 5)) & 3;
            const int kb   = ((int)(j >> 7)) & 3;
            const int gate = ((int)(j >> 9)) & 3;
            const int kst  = ((int)(j >> 11)) & 127;
            const int nti  = (int)(j >> 18);
            const int gid = l >> 2, tig = l & 3;
            const int n = nti * 64 + np * 16 + gid;
            const int k = kst * 32 + kb * 8 + tig;
            const float* wp = (gate == 0) ? Wf : (gate == 1) ? Wi : (gate == 2) ? Wc : Wo;
            const float* s0 = wp + (size_t)n * C_DIM + k;
            v.x = f2tf32f(s0[0]);                        // B[k+tig][n]       (nt=0)
            v.y = f2tf32f(s0[4]);                        // B[k+tig+4][n]
            v.z = f2tf32f(s0[8 * C_DIM]);                // B[k+tig][n+8]     (nt=1)
            v.w = f2tf32f(s0[8 * C_DIM + 4]);            // B[k+tig+4][n+8]
            g_W[j] = v;
        }
    }
}

// issue cp.async for one K-stage (fully contiguous, coalesced): 12 chunks/thread
__device__ __forceinline__ void load_stage(int ks, int stage, int tid, uint32_t sbase,
                                           int m0, int n0)
{
    const uint32_t stg = sbase + (uint32_t)stage * (STAGE_F4 * 16);
    const float4* asrc = g_A + ((size_t)(m0 >> 7) * KSTAGES + ks) * A_F4S;
    #pragma unroll
    for (int i = 0; i < 4; i++) {
        const int c = tid + i * NTHREADS;
        CP_ASYNC16(stg + c * 16, asrc + c);
    }
    const float4* wsrc = g_W + ((size_t)(n0 >> 6) * KSTAGES + ks) * W_F4S;
    #pragma unroll
    for (int i = 0; i < 8; i++) {
        const int c = tid + i * NTHREADS;
        CP_ASYNC16(stg + A_F4S * 16 + c * 16, wsrc + c);
    }
}

__global__ void __launch_bounds__(NTHREADS, 1) lstm_mma_kernel(
    const float* __restrict__ c_prev,
    const float* __restrict__ bf, const float* __restrict__ bi,
    const float* __restrict__ bc, const float* __restrict__ bo,
    float* __restrict__ out)
{
    extern __shared__ float smemf[];
    const uint32_t sbase = smem_u32(smemf);
    const int tid = threadIdx.x;
    const int wid = tid >> 5;
    const int lane = tid & 31;
    const int wm = wid & 1;      // 2 warps over M (64 rows each, mt=4)
    const int wn = wid >> 1;     // 4 warps over N (16 cols each, nt=2)
    const int gid = lane >> 2;
    const int tig = lane & 3;
    const int m0 = blockIdx.x * TM;
    const int n0 = blockIdx.y * TN;

    // accumulators: [gate][mt=4][nt=2][4] = 128 floats
    float acc[4][4][2][4];
    #pragma unroll
    for (int g = 0; g < 4; g++)
        #pragma unroll
        for (int mt = 0; mt < 4; mt++)
            #pragma unroll
            for (int nt = 0; nt < 2; nt++)
                #pragma unroll
                for (int r = 0; r < 4; r++) acc[g][mt][nt][r] = 0.0f;

    // prologue: stages 0 and 1 in flight (separate groups)
    load_stage(0, 0, tid, sbase, m0, n0);
    CP_COMMIT();
    load_stage(1, 1, tid, sbase, m0, n0);
    CP_COMMIT();

    #pragma unroll 2
    for (int ks = 0; ks < KSTAGES; ks++) {
        const bool even = (ks & 1) == 0;
        if (even) {
            // barrier every 2 stages: publishes stages ks and ks+1,
            // and frees buffers (ks-2)&3, (ks-1)&3 for the next load window
            CP_WAITN(0);
            __syncthreads();
        }
        const float4* As4 = (const float4*)(smemf + (ks & (NS - 1)) * (STAGE_F4 * 4));
        const float4* Ws4 = As4 + A_F4S;

        #pragma unroll
        for (int kk = 0; kk < 4; kk++) {
            float4 af[4];
            #pragma unroll
            for (int mt = 0; mt < 4; mt++)
                af[mt] = As4[(kk * 8 + wm * 4 + mt) * 32 + lane];
            #pragma unroll
            for (int g = 0; g < 4; g++) {
                const float4 wv = Ws4[g * 512 + (kk * 4 + wn) * 32 + lane];
                uint32_t b0[2], b1[2];
                b0[0] = __float_as_uint(wv.x); b0[1] = __float_as_uint(wv.y);
                b1[0] = __float_as_uint(wv.z); b1[1] = __float_as_uint(wv.w);
                #pragma unroll
                for (int mt = 0; mt < 4; mt++) {
                    mma_tf32(acc[g][mt][0], (const uint32_t*)&af[mt], b0);
                    mma_tf32(acc[g][mt][1], (const uint32_t*)&af[mt], b1);
                }
            }
            // even iterations issue the next 2-stage load window, spread mid-stage
            if (even) {
                if (kk == 0 && ks + 2 < KSTAGES)
                    load_stage(ks + 2, (ks + 2) & (NS - 1), tid, sbase, m0, n0);
                if (kk == 2 && ks + 2 < KSTAGES) {
                    if (ks + 3 < KSTAGES)
                        load_stage(ks + 3, (ks + 3) & (NS - 1), tid, sbase, m0, n0);
                    CP_COMMIT();   // one group covering both stages of the window
                }
            }
        }
    }

    // ---------------- fused LSTM epilogue (registers only) ----------------
    #pragma unroll
    for (int nt = 0; nt < 2; nt++) {
        const int col = n0 + wn * 16 + nt * 8 + tig * 2;
        const float2 bf2 = *(const float2*)(bf + col);
        const float2 bi2 = *(const float2*)(bi + col);
        const float2 bc2 = *(const float2*)(bc + col);
        const float2 bo2 = *(const float2*)(bo + col);
        #pragma unroll
        for (int mt = 0; mt < 4; mt++) {
            const int row0 = m0 + wm * 64 + mt * 16 + gid;
            #pragma unroll
            for (int half = 0; half < 2; half++) {
                const int row = row0 + half * 8;
                const int ci = half * 2;
                const float2 cp = *(const float2*)(c_prev + (size_t)row * H_DIM + col);
                float hh[2], cc[2];
                #pragma unroll
                for (int j = 0; j < 2; j++) {
                    const float gf = acc[0][mt][nt][ci + j] + (j ? bf2.y : bf2.x);
                    const float gi = acc[1][mt][nt][ci + j] + (j ? bi2.y : bi2.x);
                    const float gc = acc[2][mt][nt][ci + j] + (j ? bc2.y : bc2.x);
                    const float go = acc[3][mt][nt][ci + j] + (j ? bo2.y : bo2.x);
                    const float f = sigmoidf_(gf);
                    const float i = sigmoidf_(gi);
                    const float ct = tanhf_(gc);
                    const float o = sigmoidf_(go);
                    const float c = f * (j ? cp.y : cp.x) + i * ct;
                    cc[j] = c;
                    hh[j] = o * tanhf_(c);
                }
                *(float2*)(out + (size_t)row * H_DIM + col) = make_float2(hh[0], hh[1]);
                *(float2*)(out + HOUT_OFF + (size_t)row * H_DIM + col) = make_float2(cc[0], cc[1]);
            }
        }
    }
}

extern "C" void kernel_launch(void* const* d_in, const int* in_sizes, int n_in,
                              void* d_out, int out_size) {
    const float* x_t    = (const float*)d_in[0];
    const float* h_prev = (const float*)d_in[1];
    const float* c_prev = (const float*)d_in[2];
    const float* W_f    = (const float*)d_in[3];
    const float* b_f    = (const float*)d_in[4];
    const float* W_i    = (const float*)d_in[5];
    const float* b_i    = (const float*)d_in[6];
    const float* W_c    = (const float*)d_in[7];
    const float* b_c    = (const float*)d_in[8];
    const float* W_o    = (const float*)d_in[9];
    const float* b_o    = (const float*)d_in[10];
    float* out = (float*)d_out;

    // 1) round to tf32 + permute to fragment-major layout
    prepass_kernel<<<4096, 256>>>(x_t, h_prev, W_f, W_i, W_c, W_o);

    // 2) fused GEMM + LSTM epilogue (barrier every 2 K-stages)
    cudaFuncSetAttribute(lstm_mma_kernel,
                         cudaFuncAttributeMaxDynamicSharedMemorySize, SMEM_TOTAL);
    dim3 grid(B_DIM / TM, H_DIM / TN);   // (32, 32)
    lstm_mma_kernel<<<grid, NTHREADS, SMEM_TOTAL>>>(
        c_prev, b_f, b_i, b_c, b_o, out);
}

// round 16
// speedup vs baseline: 2.6071x; 1.7983x over previous
#include <cuda_runtime.h>
#include <cuda_fp16.h>
#include <cstdint>

// ---------------- problem constants ----------------
#define B_DIM 4096
#define H_DIM 2048
#define C_DIM 4096              // K dimension (H + I)
#define TM 128                  // CTA M tile
#define TN 64                   // CTA N tile (per gate; x4 gates)
#define TK 64                   // K per stage
#define KSTAGES (C_DIM / TK)    // 64
#define NS 4                    // pipeline buffers; barrier every 2 stages
#define NTHREADS 256            // 8 warps: wm(2) x wn(4); mt=4, nt=2

// fragment-major smem per stage (fp16): A = 1024 uint4 (16 KB), W = 2048 uint4 (32 KB)
#define A_U4S 1024
#define W_U4S 2048
#define STAGE_U4 (A_U4S + W_U4S)                  // 3072 uint4 = 48 KB
#define SMEM_TOTAL (NS * STAGE_U4 * 16)           // 196608 B

#define HOUT_OFF 8388608        // 4096*2048 ; c_t follows h_t in d_out

// ---------- fp16 fragment-permuted operand scratch ----------
// g_A: [mtile(32)][kstage(64)][kb(4)][bm(8)][lane(32)] uint4  (32 MB)
// g_W: [ntile(32)][kstage(64)][gate(4)][kb(4)][np(4)][lane(32)] uint4 (64 MB)
__device__ uint4 g_A[32ll * 64 * 1024];
__device__ uint4 g_W[32ll * 64 * 2048];

__device__ __forceinline__ uint32_t smem_u32(const void* p) {
    uint32_t a;
    asm("{ .reg .u64 t; cvta.to.shared.u64 t, %1; cvt.u32.u64 %0, t; }" : "=r"(a) : "l"(p));
    return a;
}

#define CP_ASYNC16(dst, src) \
    asm volatile("cp.async.cg.shared.global [%0], [%1], 16;" :: "r"(dst), "l"(src) : "memory")
#define CP_COMMIT() asm volatile("cp.async.commit_group;" ::: "memory")
#define CP_WAITN(n) asm volatile("cp.async.wait_group %0;" :: "n"(n) : "memory")

__device__ __forceinline__ uint32_t pack_h2(float a, float b) {
    __half2 h = __halves2half2(__float2half_rn(a), __float2half_rn(b));
    return *(uint32_t*)&h;
}

__device__ __forceinline__ void mma_f16(float* c, const uint32_t* a, const uint32_t* b) {
    asm volatile(
        "mma.sync.aligned.m16n8k16.row.col.f32.f16.f16.f32 "
        "{%0,%1,%2,%3}, {%4,%5,%6,%7}, {%8,%9}, {%0,%1,%2,%3};"
        : "+f"(c[0]), "+f"(c[1]), "+f"(c[2]), "+f"(c[3])
        : "r"(a[0]), "r"(a[1]), "r"(a[2]), "r"(a[3]), "r"(b[0]), "r"(b[1]));
}

__device__ __forceinline__ float sigmoidf_(float x) {
    return 1.0f / (1.0f + __expf(-x));
}
__device__ __forceinline__ float tanhf_(float x) {
    float a = fabsf(x);
    float e = __expf(-2.0f * a);
    float t = (1.0f - e) / (1.0f + e);
    return x < 0.0f ? -t : t;
}

// ---------------- prepass: convert to fp16 AND permute to fragment-major ----------
#define A_CHUNKS 2097152          // 32*64*4*8*32
#define W_CHUNKS 4194304          // 32*64*4*4*4*32
#define TOT_CHUNKS (A_CHUNKS + W_CHUNKS)

__global__ void __launch_bounds__(256) prepass_kernel(
    const float* __restrict__ x_t, const float* __restrict__ h_prev,
    const float* __restrict__ Wf, const float* __restrict__ Wi,
    const float* __restrict__ Wc, const float* __restrict__ Wo)
{
    const int stride = gridDim.x * blockDim.x;
    for (long long i = blockIdx.x * blockDim.x + threadIdx.x; i < TOT_CHUNKS; i += stride) {
        uint4 v;
        if (i < A_CHUNKS) {
            // [mtile][kstage(64)][kb(4)][bm(8)][lane]
            const int l   = (int)(i) & 31;
            const int bm  = ((int)(i >> 5)) & 7;
            const int kb  = ((int)(i >> 8)) & 3;
            const int kst = ((int)(i >> 10)) & 63;
            const int mti = (int)(i >> 16);
            const int gid = l >> 2, tig = l & 3;
            const int r = mti * 128 + bm * 16 + gid;
            const int k0 = kst * 64 + kb * 16 + 2 * tig;   // 16-blk never crosses 2048
            const float* s0;  // row r
            const float* s1;  // row r+8
            if (k0 < H_DIM) {
                s0 = h_prev + (size_t)r * H_DIM + k0;
                s1 = h_prev + (size_t)(r + 8) * H_DIM + k0;
            } else {
                s0 = x_t + (size_t)r * H_DIM + (k0 - H_DIM);
                s1 = x_t + (size_t)(r + 8) * H_DIM + (k0 - H_DIM);
            }
            v.x = pack_h2(s0[0], s0[1]);     // a0: row r,   k0..k0+1
            v.y = pack_h2(s1[0], s1[1]);     // a1: row r+8, k0..k0+1
            v.z = pack_h2(s0[8], s0[9]);     // a2: row r,   k0+8..k0+9
            v.w = pack_h2(s1[8], s1[9]);     // a3: row r+8, k0+8..k0+9
            g_A[i] = v;
        } else {
            // [ntile][kstage(64)][gate(4)][kb(4)][np(4)][lane]
            const long long j = i - A_CHUNKS;
            const int l    = (int)(j) & 31;
            const int np   = ((int)(j >> 5)) & 3;
            const int kb   = ((int)(j >> 7)) & 3;
            const int gate = ((int)(j >> 9)) & 3;
            const int kst  = ((int)(j >> 11)) & 63;
            const int nti  = (int)(j >> 17);
            const int gid = l >> 2, tig = l & 3;
            const int k0 = kst * 64 + kb * 16 + 2 * tig;
            const int n0 = nti * 64 + np * 16 + gid;       // nt=0 column
            const int n1 = n0 + 8;                         // nt=1 column
            const float* wp = (gate == 0) ? Wf : (gate == 1) ? Wi : (gate == 2) ? Wc : Wo;
            const float* r0 = wp + (size_t)n0 * C_DIM + k0;
            const float* r1 = wp + (size_t)n1 * C_DIM + k0;
            v.x = pack_h2(r0[0], r0[1]);     // b0(nt=0): k0..k0+1
            v.y = pack_h2(r0[8], r0[9]);     // b1(nt=0): k0+8..k0+9
            v.z = pack_h2(r1[0], r1[1]);     // b0(nt=1)
            v.w = pack_h2(r1[8], r1[9]);     // b1(nt=1)
            g_W[j] = v;
        }
    }
}

// issue cp.async for one K-stage (fully contiguous, coalesced): 12 chunks/thread
__device__ __forceinline__ void load_stage(int ks, int stage, int tid, uint32_t sbase,
                                           int m0, int n0)
{
    const uint32_t stg = sbase + (uint32_t)stage * (STAGE_U4 * 16);
    const uint4* asrc = g_A + ((size_t)(m0 >> 7) * KSTAGES + ks) * A_U4S;
    #pragma unroll
    for (int i = 0; i < 4; i++) {
        const int c = tid + i * NTHREADS;
        CP_ASYNC16(stg + c * 16, asrc + c);
    }
    const uint4* wsrc = g_W + ((size_t)(n0 >> 6) * KSTAGES + ks) * W_U4S;
    #pragma unroll
    for (int i = 0; i < 8; i++) {
        const int c = tid + i * NTHREADS;
        CP_ASYNC16(stg + A_U4S * 16 + c * 16, wsrc + c);
    }
}

__global__ void __launch_bounds__(NTHREADS, 1) lstm_mma_kernel(
    const float* __restrict__ c_prev,
    const float* __restrict__ bf, const float* __restrict__ bi,
    const float* __restrict__ bc, const float* __restrict__ bo,
    float* __restrict__ out)
{
    extern __shared__ float smemf[];
    const uint32_t sbase = smem_u32(smemf);
    const int tid = threadIdx.x;
    const int wid = tid >> 5;
    const int lane = tid & 31;
    const int wm = wid & 1;      // 2 warps over M (64 rows each, mt=4)
    const int wn = wid >> 1;     // 4 warps over N (16 cols each, nt=2)
    const int gid = lane >> 2;
    const int tig = lane & 3;
    const int m0 = blockIdx.x * TM;
    const int n0 = blockIdx.y * TN;

    // accumulators: [gate][mt=4][nt=2][4] = 128 floats
    float acc[4][4][2][4];
    #pragma unroll
    for (int g = 0; g < 4; g++)
        #pragma unroll
        for (int mt = 0; mt < 4; mt++)
            #pragma unroll
            for (int nt = 0; nt < 2; nt++)
                #pragma unroll
                for (int r = 0; r < 4; r++) acc[g][mt][nt][r] = 0.0f;

    // prologue: stages 0 and 1 in flight (separate groups)
    load_stage(0, 0, tid, sbase, m0, n0);
    CP_COMMIT();
    load_stage(1, 1, tid, sbase, m0, n0);
    CP_COMMIT();

    #pragma unroll 2
    for (int ks = 0; ks < KSTAGES; ks++) {
        const bool even = (ks & 1) == 0;
        if (even) {
            CP_WAITN(0);          // stages ks, ks+1 resident
            __syncthreads();      // publish; frees buffers (ks-2)&3,(ks-1)&3
        }
        const uint4* As4 = (const uint4*)((const char*)smemf + (ks & (NS - 1)) * (STAGE_U4 * 16));
        const uint4* Ws4 = As4 + A_U4S;

        #pragma unroll
        for (int kk = 0; kk < 4; kk++) {     // 4 x k16 blocks
            uint4 af[4];
            #pragma unroll
            for (int mt = 0; mt < 4; mt++)
                af[mt] = As4[(kk * 8 + wm * 4 + mt) * 32 + lane];
            #pragma unroll
            for (int g = 0; g < 4; g++) {
                const uint4 wv = Ws4[g * 512 + (kk * 4 + wn) * 32 + lane];
                uint32_t b0[2], b1[2];
                b0[0] = wv.x; b0[1] = wv.y;
                b1[0] = wv.z; b1[1] = wv.w;
                #pragma unroll
                for (int mt = 0; mt < 4; mt++) {
                    mma_f16(acc[g][mt][0], (const uint32_t*)&af[mt], b0);
                    mma_f16(acc[g][mt][1], (const uint32_t*)&af[mt], b1);
                }
            }
            // even iterations issue the next 2-stage load window, spread mid-stage
            if (even) {
                if (kk == 0 && ks + 2 < KSTAGES)
                    load_stage(ks + 2, (ks + 2) & (NS - 1), tid, sbase, m0, n0);
                if (kk == 2 && ks + 2 < KSTAGES) {
                    if (ks + 3 < KSTAGES)
                        load_stage(ks + 3, (ks + 3) & (NS - 1), tid, sbase, m0, n0);
                    CP_COMMIT();   // one group covering both stages of the window
                }
            }
        }
    }

    // ---------------- fused LSTM epilogue (registers only) ----------------
    #pragma unroll
    for (int nt = 0; nt < 2; nt++) {
        const int col = n0 + wn * 16 + nt * 8 + tig * 2;
        const float2 bf2 = *(const float2*)(bf + col);
        const float2 bi2 = *(const float2*)(bi + col);
        const float2 bc2 = *(const float2*)(bc + col);
        const float2 bo2 = *(const float2*)(bo + col);
        #pragma unroll
        for (int mt = 0; mt < 4; mt++) {
            const int row0 = m0 + wm * 64 + mt * 16 + gid;
            #pragma unroll
            for (int half = 0; half < 2; half++) {
                const int row = row0 + half * 8;
                const int ci = half * 2;
                const float2 cp = *(const float2*)(c_prev + (size_t)row * H_DIM + col);
                float hh[2], cc[2];
                #pragma unroll
                for (int j = 0; j < 2; j++) {
                    const float gf = acc[0][mt][nt][ci + j] + (j ? bf2.y : bf2.x);
                    const float gi = acc[1][mt][nt][ci + j] + (j ? bi2.y : bi2.x);
                    const float gc = acc[2][mt][nt][ci + j] + (j ? bc2.y : bc2.x);
                    const float go = acc[3][mt][nt][ci + j] + (j ? bo2.y : bo2.x);
                    const float f = sigmoidf_(gf);
                    const float i = sigmoidf_(gi);
                    const float ct = tanhf_(gc);
                    const float o = sigmoidf_(go);
                    const float c = f * (j ? cp.y : cp.x) + i * ct;
                    cc[j] = c;
                    hh[j] = o * tanhf_(c);
                }
                *(float2*)(out + (size_t)row * H_DIM + col) = make_float2(hh[0], hh[1]);
                *(float2*)(out + HOUT_OFF + (size_t)row * H_DIM + col) = make_float2(cc[0], cc[1]);
            }
        }
    }
}

extern "C" void kernel_launch(void* const* d_in, const int* in_sizes, int n_in,
                              void* d_out, int out_size) {
    const float* x_t    = (const float*)d_in[0];
    const float* h_prev = (const float*)d_in[1];
    const float* c_prev = (const float*)d_in[2];
    const float* W_f    = (const float*)d_in[3];
    const float* b_f    = (const float*)d_in[4];
    const float* W_i    = (const float*)d_in[5];
    const float* b_i    = (const float*)d_in[6];
    const float* W_c    = (const float*)d_in[7];
    const float* b_c    = (const float*)d_in[8];
    const float* W_o    = (const float*)d_in[9];
    const float* b_o    = (const float*)d_in[10];
    float* out = (float*)d_out;

    // 1) convert to fp16 + permute to fragment-major layout
    prepass_kernel<<<4096, 256>>>(x_t, h_prev, W_f, W_i, W_c, W_o);

    // 2) fused GEMM + LSTM epilogue (fp16 m16n8k16, fp32 accumulate)
    cudaFuncSetAttribute(lstm_mma_kernel,
                         cudaFuncAttributeMaxDynamicSharedMemorySize, SMEM_TOTAL);
    dim3 grid(B_DIM / TM, H_DIM / TN);   // (32, 32)
    lstm_mma_kernel<<<grid, NTHREADS, SMEM_TOTAL>>>(
        c_prev, b_f, b_i, b_c, b_o, out);
}